// round 2
// baseline (speedup 1.0000x reference)
#include <cuda_runtime.h>

// WaveletDWTLayer: fused db4 DWT + 2x IDWT, one CTA per batch row.
// Outputs concatenated: cA [B,1,2051] | cDs [B,2,1,4096] | R [B,1,1,8186]

namespace {
constexpr int L    = 4096;        // signal length
constexpr int NC   = 2051;        // dwt coeff count = (L+7)/2
constexpr int EXT  = L + 13;      // symmetric-extended length (4109)
constexpr int RLEN = 2 * L - 6;   // final idwt output length (8186)

// REC_LO (analysis filter in the reference's conv — lax conv = cross-correlation)
__device__ constexpr float RLO[8] = {
     0.23037781330885523f,  0.7148465705525415f,   0.6308807679295904f,  -0.02798376941698385f,
    -0.18703481171888114f,  0.030841381835986965f, 0.032883011666982945f,-0.010597401784997278f};
// REC_HI[k] = (-1)^k * REC_LO[7-k]
__device__ constexpr float RHI[8] = {
    -0.010597401784997278f,-0.032883011666982945f, 0.030841381835986965f, 0.18703481171888114f,
    -0.02798376941698385f, -0.6308807679295904f,   0.7148465705525415f,  -0.23037781330885523f};
// DEC_LO[k] = REC_LO[7-k]
__device__ constexpr float DLO[8] = {
    -0.010597401784997278f, 0.032883011666982945f, 0.030841381835986965f,-0.18703481171888114f,
    -0.02798376941698385f,  0.6308807679295904f,   0.7148465705525415f,   0.23037781330885523f};
// DEC_HI[k] = REC_HI[7-k]
__device__ constexpr float DHI[8] = {
    -0.23037781330885523f,  0.7148465705525415f,  -0.6308807679295904f,  -0.02798376941698385f,
     0.18703481171888114f,  0.030841381835986965f,-0.032883011666982945f,-0.010597401784997278f};
} // namespace

__global__ __launch_bounds__(256)
void wavelet_fused_kernel(const float* __restrict__ x1,
                          const float* __restrict__ x2,
                          float* __restrict__ out, int B)
{
    __shared__ alignas(16) float s_x[EXT + 3]; // phase 1-2: ext(x1); phase 3+: x2 row
    __shared__ float s_cD[NC + 1];
    __shared__ float s_a[L];

    const int b = blockIdx.x;
    const int t = threadIdx.x;

    const float* __restrict__ x1row = x1 + (size_t)b * L;
    const float* __restrict__ x2row = x2 + (size_t)b * L;

    float* __restrict__ outA = out + (size_t)b * NC;
    float* __restrict__ outD = out + (size_t)B * NC + (size_t)b * (2 * L);
    float* __restrict__ outR = out + (size_t)B * NC + (size_t)B * (2 * L)
                                   + (size_t)b * RLEN;

    // ---- Phase 1: symmetric-extended x1 into smem ----
    // ext = [x5..x0 | x0..x_{L-1} | x_{L-1}..x_{L-7}]  (length L+13)
    for (int i4 = t; i4 < L / 4; i4 += 256) {      // main body, float4 gmem loads
        float4 v = reinterpret_cast<const float4*>(x1row)[i4];
        int j = 6 + 4 * i4;
        s_x[j] = v.x; s_x[j + 1] = v.y; s_x[j + 2] = v.z; s_x[j + 3] = v.w;
    }
    if (t < 6)            s_x[t]     = x1row[5 - t];       // head: x5..x0
    else if (t < 13)      s_x[L + t] = x1row[L + 5 - t];   // tail: x_{L-1}..x_{L-7}
    __syncthreads();

    // ---- Phase 2: DWT (stride-2, 8-tap, cross-correlation) ----
    for (int i = t; i < NC; i += 256) {
        float lo = 0.f, hi = 0.f;
#pragma unroll
        for (int k = 0; k < 8; k++) {
            float v = s_x[2 * i + k];
            lo = fmaf(v, RLO[k], lo);
            hi = fmaf(v, RHI[k], hi);
        }
        outA[i]     = lo;
        s_cD[i]     = hi;
        outD[L + i] = hi;          // cDs channel 1
    }
    for (int i = NC + t; i < L; i += 256) outD[L + i] = 10.1f;  // FILLER
    __syncthreads();

    // ---- Phase 3: a = idwt(0, cD) -> s_a ; reload s_x with x2 ; copy x2 -> cDs ch 0 ----
    // idwt output i: u = i>>1; even i uses taps {1,3,5,7}, odd uses {0,2,4,6};
    // out length 2n-6 guarantees no boundary clipping (max index u+3 = n-1).
    for (int u = t; u < L / 2; u += 256) {
        float c0 = s_cD[u], c1 = s_cD[u + 1], c2 = s_cD[u + 2], c3 = s_cD[u + 3];
        float e = fmaf(c0, DHI[1], fmaf(c1, DHI[3], fmaf(c2, DHI[5], c3 * DHI[7])));
        float o = fmaf(c0, DHI[0], fmaf(c1, DHI[2], fmaf(c2, DHI[4], c3 * DHI[6])));
        s_a[2 * u]     = e;
        s_a[2 * u + 1] = o;
    }
    for (int i4 = t; i4 < L / 4; i4 += 256) {      // x2 -> smem + cDs ch0, float4 both sides
        float4 v = reinterpret_cast<const float4*>(x2row)[i4];
        reinterpret_cast<float4*>(s_x)[i4]  = v;
        reinterpret_cast<float4*>(outD)[i4] = v;
    }
    __syncthreads();

    // ---- Phase 4: R = idwt(a, x2), paired outputs + float2 stores ----
    for (int u = t; u < RLEN / 2; u += 256) {
        float a0 = s_a[u], a1 = s_a[u + 1], a2 = s_a[u + 2], a3 = s_a[u + 3];
        float b0 = s_x[u], b1 = s_x[u + 1], b2 = s_x[u + 2], b3 = s_x[u + 3];

        float e = fmaf(a0, DLO[1], fmaf(a1, DLO[3], fmaf(a2, DLO[5], a3 * DLO[7])));
        e = fmaf(b0, DHI[1], fmaf(b1, DHI[3], fmaf(b2, DHI[5], fmaf(b3, DHI[7], e))));
        float o = fmaf(a0, DLO[0], fmaf(a1, DLO[2], fmaf(a2, DLO[4], a3 * DLO[6])));
        o = fmaf(b0, DHI[0], fmaf(b1, DHI[2], fmaf(b2, DHI[4], fmaf(b3, DHI[6], o))));

        *reinterpret_cast<float2*>(outR + 2 * u) = make_float2(e, o);
    }
}

extern "C" void kernel_launch(void* const* d_in, const int* in_sizes, int n_in,
                              void* d_out, int out_size) {
    const float* x1 = (const float*)d_in[0];   // [B,1,L]
    const float* x2 = (const float*)d_in[1];   // [B,1,1,L]
    // d_in[2] = x3 [B,1,1,1] is unused by the reference math.
    int B = in_sizes[2];                       // x3 has exactly B elements
    wavelet_fused_kernel<<<B, 256>>>(x1, x2, (float*)d_out, B);
}